// round 10
// baseline (speedup 1.0000x reference)
#include <cuda_runtime.h>
#include <math.h>

typedef unsigned long long u64;

// ---- packed f32x2 helpers (sm_100+) ----------------------------------------
__device__ __forceinline__ u64 pack2(float lo, float hi) {
    u64 r;
    asm("mov.b64 %0, {%1, %2};" : "=l"(r) : "f"(lo), "f"(hi));
    return r;
}
__device__ __forceinline__ void fma2(u64 &d, u64 a, u64 b) {
    asm("fma.rn.f32x2 %0, %1, %2, %0;" : "+l"(d) : "l"(a), "l"(b));
}
__device__ __forceinline__ float2 unpack2(u64 v) {
    float lo, hi;
    asm("mov.b64 {%0, %1}, %2;" : "=f"(lo), "=f"(hi) : "l"(v));
    return make_float2(lo, hi);
}

static constexpr int IN_DIM  = 592;
static constexpr int W_NUMEL = 21760;
static constexpr int NT      = 256;

// out[z, w*DIM+i] = pw * sum_u W[u,w] * x[z, u*DIM+i]
//
// x slice staged in smem as DUPLICATED u64 pairs (v,v) with pw folded in →
// the broadcast operand of fma.rn.f32x2 is a single LDS.64, zero MOVs.
// Weights read straight from global as natural (w, w+1) u64 pairs via __ldg
// (L1-resident across CTAs, no per-CTA staging traffic, no bank conflicts).
// Thread tile: TR rows of r=(z,i) x TW weight columns, columns strided by NWT
// pairs so each warp-wide LDG.64 is one contiguous cache line.
template<int MUL, int DIM, int XOFF, int WOFF, int ZT, int TR, int TW>
__global__ __launch_bounds__(NT)
void irrep_kernel(const float* __restrict__ x,
                  const float* __restrict__ wts,
                  float* __restrict__ out,
                  int batch, float pw)
{
    constexpr int RL  = MUL * DIM;
    constexpr int RLP = RL + 2;        // u64 row stride: row delta = 4 banks mod 32
    constexpr int TW2 = TW / 2;
    constexpr int NWT = MUL / TW;      // thread groups along w (strided mapping)
    constexpr int NRT = NT / NWT;      // thread groups along r
    constexpr int RL4 = RL / 4;
    constexpr int LDO = RL + 4;        // float row stride for output staging
    static_assert(NRT * TR == ZT * DIM, "tile covers CTA rows");
    static_assert(TR % DIM == 0, "whole z rows per thread");
    static_assert((TW & 1) == 0, "f32x2 needs even TW");

    extern __shared__ u64 smem[];
    u64* Xd = smem;                    // [ZT][RLP] duplicated pairs, pw folded

    const int tid = threadIdx.x;
    const int z0  = blockIdx.x * ZT;
    const int zc  = min(ZT, batch - z0);

    // Stage x: coalesced float4 reads, duplicated u64 writes, pw folded in.
    for (int idx = tid; idx < zc * RL4; idx += NT) {
        int z = idx / RL4, c = idx - z * RL4;
        float4 v = *(const float4*)&x[(size_t)(z0 + z) * IN_DIM + XOFF + 4 * c];
        u64* p = &Xd[z * RLP + 4 * c];
        float a = v.x * pw, b = v.y * pw, cc = v.z * pw, d = v.w * pw;
        p[0] = pack2(a, a);
        p[1] = pack2(b, b);
        p[2] = pack2(cc, cc);
        p[3] = pack2(d, d);
    }
    if (zc < ZT) {
        for (int idx = tid; idx < (ZT - zc) * RLP; idx += NT)
            Xd[zc * RLP + idx] = 0ull;
    }
    __syncthreads();

    const int wt = tid % NWT;
    const int rt = tid / NWT;
    const int zb = (rt * TR) / DIM;

    const u64* __restrict__ Wg =
        reinterpret_cast<const u64*>(wts + WOFF) + wt;   // u64 = (W[u,2p], W[u,2p+1])
    const u64* Xr = &Xd[zb * RLP];

    u64 acc[TR][TW2];
    #pragma unroll
    for (int k = 0; k < TR; ++k)
        #pragma unroll
        for (int j = 0; j < TW2; ++j)
            acc[k][j] = 0ull;

    #pragma unroll 4
    for (int u = 0; u < MUL; ++u) {
        u64 wp[TW2];
        #pragma unroll
        for (int j = 0; j < TW2; ++j)
            wp[j] = __ldg(Wg + (size_t)u * (MUL / 2) + j * NWT);
        u64 xv[TR];
        #pragma unroll
        for (int k = 0; k < TR; ++k) {
            const int zz = k / DIM, i = k % DIM;
            xv[k] = Xr[zz * RLP + u * DIM + i];
        }
        #pragma unroll
        for (int k = 0; k < TR; ++k)
            #pragma unroll
            for (int j = 0; j < TW2; ++j)
                fma2(acc[k][j], xv[k], wp[j]);
    }
    __syncthreads();   // all Xd reads done; reuse buffer as output staging

    // Scatter accumulators into smem (irrep-layout), then coalesced store.
    float* Os = reinterpret_cast<float*>(smem);
    #pragma unroll
    for (int k = 0; k < TR; ++k) {
        const int zz = k / DIM, i = k % DIM;
        float* orow = &Os[(zb + zz) * LDO + i];
        #pragma unroll
        for (int j = 0; j < TW2; ++j) {
            float2 v = unpack2(acc[k][j]);
            const int w0 = 2 * (wt + j * NWT);
            orow[(w0    ) * DIM] = v.x;
            orow[(w0 + 1) * DIM] = v.y;
        }
    }
    __syncthreads();

    for (int idx = tid; idx < zc * RL4; idx += NT) {
        int z = idx / RL4, c = idx - z * RL4;
        *(float4*)&out[(size_t)(z0 + z) * IN_DIM + XOFF + 4 * c] =
            *(const float4*)&Os[z * LDO + 4 * c];
    }
}

// ---- launcher ---------------------------------------------------------------
template<int MUL, int DIM, int XOFF, int WOFF, int ZT, int TR, int TW>
static void launch_block(const float* x, const float* w, float* out, int batch)
{
    constexpr int RLP = MUL * DIM + 2;
    const size_t sm = (size_t)ZT * RLP * sizeof(u64);
    auto kfn = irrep_kernel<MUL, DIM, XOFF, WOFF, ZT, TR, TW>;
    cudaFuncSetAttribute(kfn, cudaFuncAttributeMaxDynamicSharedMemorySize, (int)sm);
    const int grid = (batch + ZT - 1) / ZT;
    const float pw = (float)(1.0 / sqrt((double)MUL));
    kfn<<<grid, NT, sm>>>(x, w, out, batch, pw);
}

extern "C" void kernel_launch(void* const* d_in, const int* in_sizes, int n_in,
                              void* d_out, int out_size)
{
    const float* x = (const float*)d_in[0];
    const float* w = (const float*)d_in[1];
    int xsz = in_sizes[0];
    if (n_in >= 2 && in_sizes[0] == W_NUMEL) {   // robust to input ordering
        x = (const float*)d_in[1];
        w = (const float*)d_in[0];
        xsz = in_sizes[1];
    }
    float* out = (float*)d_out;
    const int batch = xsz / IN_DIM;

    //                 MUL DIM XOFF  WOFF  ZT  TR  TW
    launch_block<128, 1,   0,     0, 64,  4,  8>(x, w, out, batch);  // 66.6 KB smem
    launch_block< 64, 3, 128, 16384, 32,  3,  8>(x, w, out, batch);  // 49.7 KB
    launch_block< 32, 5, 320, 20480, 32,  5,  4>(x, w, out, batch);  // 41.5 KB
    launch_block< 16, 7, 480, 21504, 64,  7,  4>(x, w, out, batch);  // 58.4 KB
}

// round 11
// speedup vs baseline: 1.2079x; 1.2079x over previous
#include <cuda_runtime.h>
#include <math.h>

typedef unsigned long long u64;

// ---- packed f32x2 helpers (sm_100+) ----------------------------------------
__device__ __forceinline__ u64 dup2(float a) {
    u64 r;
    asm("mov.b64 %0, {%1, %1};" : "=l"(r) : "f"(a));
    return r;
}
__device__ __forceinline__ void fma2(u64 &d, u64 a, u64 b) {
    asm("fma.rn.f32x2 %0, %1, %2, %0;" : "+l"(d) : "l"(a), "l"(b));
}
__device__ __forceinline__ float2 unpack2(u64 v) {
    float lo, hi;
    asm("mov.b64 {%0, %1}, %2;" : "=f"(lo), "=f"(hi) : "l"(v));
    return make_float2(lo, hi);
}

static constexpr int IN_DIM  = 592;
static constexpr int W_NUMEL = 21760;
static constexpr int NT      = 256;   // 8 warps

// out[z, w*DIM+i] = pw * sum_u W[u,w] * x[z, u*DIM+i]
//
// Warp layout (the round-8 failure was crossbar-bound; this fixes the mix):
//  * every lane of a warp works on the SAME TW weight columns  -> W loads are
//    warp-broadcast LDG.64 (1 wavefront, L1-resident across CTAs)
//  * lanes span 32 consecutive z rows; smem x row stride RLP is ODD -> every
//    x LDS.32 is a single conflict-free 128B wavefront
//  * per-thread register tile TR x TW2 accumulators (f32x2) makes the fma
//    pipe the binding resource (TR*TW2/2 > TR + TW2 crossbar cycles)
template<int MUL, int DIM, int XOFF, int WOFF, int ZPT, int TW>
__global__ __launch_bounds__(NT, 2)
void irrep_kernel(const float* __restrict__ x,
                  const float* __restrict__ wts,
                  float* __restrict__ out,
                  int batch, float pw)
{
    constexpr int NW  = NT / 32;       // 8 warps
    constexpr int G   = MUL / TW;      // column groups
    constexpr int R   = NW / G;        // row groups
    constexpr int ZT  = R * 32 * ZPT;  // z rows per CTA
    constexpr int TR  = ZPT * DIM;     // accumulator rows per thread
    constexpr int TW2 = TW / 2;
    constexpr int RL  = MUL * DIM;     // floats per row slice
    constexpr int RLP = RL + 1;        // ODD smem stride for the main loop
    constexpr int LDO = RL + 2;        // even stride for output staging (8B ok)
    constexpr int RL4 = RL / 4;
    constexpr int RL2 = RL / 2;
    static_assert(G * R == NW, "warps must tile (colgrp x rowgrp)");
    static_assert((RLP & 1) == 1, "conflict-free LDS needs odd stride");
    static_assert((TW & 1) == 0, "f32x2 needs even TW");

    extern __shared__ float smem[];    // ZT * LDO floats (>= ZT * RLP)

    const int tid = threadIdx.x;
    const int z0  = blockIdx.x * ZT;
    const int zc  = min(ZT, batch - z0);

    // ---- stage x slice (pw folded in), RLP stride -------------------------
    for (int idx = tid; idx < zc * RL4; idx += NT) {
        int z = idx / RL4, c = idx - z * RL4;
        float4 v = *(const float4*)&x[(size_t)(z0 + z) * IN_DIM + XOFF + 4 * c];
        float* p = &smem[z * RLP + 4 * c];
        p[0] = v.x * pw; p[1] = v.y * pw; p[2] = v.z * pw; p[3] = v.w * pw;
    }
    if (zc < ZT) {   // tail CTA: zero so garbage never enters the math
        for (int idx = zc * RLP + tid; idx < ZT * RLP; idx += NT)
            smem[idx] = 0.f;
    }
    __syncthreads();

    // ---- main loop ---------------------------------------------------------
    const int wp = tid >> 5, ln = tid & 31;
    const int cg = wp % G,  rg = wp / G;
    const int w0 = cg * TW;
    const int zl = rg * (32 * ZPT) + ln;        // base local z (dz strides by 32)

    const u64* __restrict__ Wg =
        reinterpret_cast<const u64*>(wts + WOFF) + (w0 >> 1);

    u64 acc[TR][TW2];
    #pragma unroll
    for (int k = 0; k < TR; ++k)
        #pragma unroll
        for (int j = 0; j < TW2; ++j)
            acc[k][j] = 0ull;

    #pragma unroll 4
    for (int u = 0; u < MUL; ++u) {
        u64 wv[TW2];
        #pragma unroll
        for (int j = 0; j < TW2; ++j)            // broadcast: all lanes same addr
            wv[j] = __ldg(Wg + (size_t)u * (MUL / 2) + j);
        u64 xv[TR];
        #pragma unroll
        for (int dz = 0; dz < ZPT; ++dz)
            #pragma unroll
            for (int i = 0; i < DIM; ++i)        // 1 wavefront per LDS.32
                xv[dz * DIM + i] = dup2(smem[(zl + dz * 32) * RLP + u * DIM + i]);
        #pragma unroll
        for (int k = 0; k < TR; ++k)
            #pragma unroll
            for (int j = 0; j < TW2; ++j)
                fma2(acc[k][j], xv[k], wv[j]);
    }
    __syncthreads();   // x reads done; reuse buffer for output staging

    // ---- scatter accumulators to irrep layout, then coalesced store -------
    #pragma unroll
    for (int dz = 0; dz < ZPT; ++dz) {
        float* orow = &smem[(zl + dz * 32) * LDO];
        #pragma unroll
        for (int i = 0; i < DIM; ++i)
            #pragma unroll
            for (int j = 0; j < TW2; ++j) {
                float2 v = unpack2(acc[dz * DIM + i][j]);
                orow[(w0 + 2 * j    ) * DIM + i] = v.x;
                orow[(w0 + 2 * j + 1) * DIM + i] = v.y;
            }
    }
    __syncthreads();

    for (int idx = tid; idx < zc * RL2; idx += NT) {
        int z = idx / RL2, c = idx - z * RL2;
        *(float2*)&out[(size_t)(z0 + z) * IN_DIM + XOFF + 2 * c] =
            *(const float2*)&smem[z * LDO + 2 * c];
    }
}

// ---- launcher ---------------------------------------------------------------
template<int MUL, int DIM, int XOFF, int WOFF, int ZPT, int TW>
static void launch_block(const float* x, const float* w, float* out, int batch)
{
    constexpr int G  = MUL / TW;
    constexpr int R  = (NT / 32) / G;
    constexpr int ZT = R * 32 * ZPT;
    constexpr int LDO = MUL * DIM + 2;
    const size_t sm = (size_t)ZT * LDO * sizeof(float);
    auto kfn = irrep_kernel<MUL, DIM, XOFF, WOFF, ZPT, TW>;
    cudaFuncSetAttribute(kfn, cudaFuncAttributeMaxDynamicSharedMemorySize, (int)sm);
    const int grid = (batch + ZT - 1) / ZT;
    const float pw = (float)(1.0 / sqrt((double)MUL));
    kfn<<<grid, NT, sm>>>(x, w, out, batch, pw);
}

extern "C" void kernel_launch(void* const* d_in, const int* in_sizes, int n_in,
                              void* d_out, int out_size)
{
    (void)out_size;
    const float* x = (const float*)d_in[0];
    const float* w = (const float*)d_in[1];
    int xsz = in_sizes[0];
    if (n_in >= 2 && in_sizes[0] == W_NUMEL) {   // robust to input ordering
        x = (const float*)d_in[1];
        w = (const float*)d_in[0];
        xsz = in_sizes[1];
    }
    float* out = (float*)d_out;
    const int batch = xsz / IN_DIM;

    //                 MUL DIM XOFF  WOFF ZPT TW   (ZT, TRxTW2, smem)
    launch_block<128, 1,   0,     0,  4, 16>(x, w, out, batch); // 128z, 4x8, 66.6KB
    launch_block< 64, 3, 128, 16384,  2,  8>(x, w, out, batch); //  64z, 6x4, 49.7KB
    launch_block< 32, 5, 320, 20480,  1,  8>(x, w, out, batch); //  64z, 5x4, 41.5KB
    launch_block< 16, 7, 480, 21504,  1,  8>(x, w, out, batch); // 128z, 7x4, 58.4KB
}

// round 12
// speedup vs baseline: 1.2081x; 1.0001x over previous
#include <cuda_runtime.h>
#include <math.h>

typedef unsigned long long u64;

// ---- packed f32x2 helpers (sm_100+) ----------------------------------------
__device__ __forceinline__ u64 dup2(float a) {
    u64 r;
    asm("mov.b64 %0, {%1, %1};" : "=l"(r) : "f"(a));
    return r;
}
__device__ __forceinline__ void fma2(u64 &d, u64 a, u64 b) {
    asm("fma.rn.f32x2 %0, %1, %2, %0;" : "+l"(d) : "l"(a), "l"(b));
}
__device__ __forceinline__ float2 unpack2(u64 v) {
    float lo, hi;
    asm("mov.b64 {%0, %1}, %2;" : "=f"(lo), "=f"(hi) : "l"(v));
    return make_float2(lo, hi);
}

static constexpr int IN_DIM  = 592;
static constexpr int W_NUMEL = 21760;
static constexpr int NT      = 256;   // 8 warps

// out[z, w*DIM+i] = pw * sum_u W[u,w] * x[z, u*DIM+i]
//
// Warp layout (the round-8 failure was crossbar-bound; this fixes the mix):
//  * every lane of a warp works on the SAME TW weight columns  -> W loads are
//    warp-broadcast LDG.64 (1 wavefront, L1-resident across CTAs)
//  * lanes span 32 consecutive z rows; smem x row stride RLP is ODD -> every
//    x LDS.32 is a single conflict-free 128B wavefront
//  * per-thread register tile TR x TW2 accumulators (f32x2) makes the fma
//    pipe the binding resource (TR*TW2/2 > TR + TW2 crossbar cycles)
template<int MUL, int DIM, int XOFF, int WOFF, int ZPT, int TW>
__global__ __launch_bounds__(NT, 2)
void irrep_kernel(const float* __restrict__ x,
                  const float* __restrict__ wts,
                  float* __restrict__ out,
                  int batch, float pw)
{
    constexpr int NW  = NT / 32;       // 8 warps
    constexpr int G   = MUL / TW;      // column groups
    constexpr int R   = NW / G;        // row groups
    constexpr int ZT  = R * 32 * ZPT;  // z rows per CTA
    constexpr int TR  = ZPT * DIM;     // accumulator rows per thread
    constexpr int TW2 = TW / 2;
    constexpr int RL  = MUL * DIM;     // floats per row slice
    constexpr int RLP = RL + 1;        // ODD smem stride for the main loop
    constexpr int LDO = RL + 2;        // even stride for output staging (8B ok)
    constexpr int RL4 = RL / 4;
    constexpr int RL2 = RL / 2;
    static_assert(G * R == NW, "warps must tile (colgrp x rowgrp)");
    static_assert((RLP & 1) == 1, "conflict-free LDS needs odd stride");
    static_assert((TW & 1) == 0, "f32x2 needs even TW");

    extern __shared__ float smem[];    // ZT * LDO floats (>= ZT * RLP)

    const int tid = threadIdx.x;
    const int z0  = blockIdx.x * ZT;
    const int zc  = min(ZT, batch - z0);

    // ---- stage x slice (pw folded in), RLP stride -------------------------
    for (int idx = tid; idx < zc * RL4; idx += NT) {
        int z = idx / RL4, c = idx - z * RL4;
        float4 v = *(const float4*)&x[(size_t)(z0 + z) * IN_DIM + XOFF + 4 * c];
        float* p = &smem[z * RLP + 4 * c];
        p[0] = v.x * pw; p[1] = v.y * pw; p[2] = v.z * pw; p[3] = v.w * pw;
    }
    if (zc < ZT) {   // tail CTA: zero so garbage never enters the math
        for (int idx = zc * RLP + tid; idx < ZT * RLP; idx += NT)
            smem[idx] = 0.f;
    }
    __syncthreads();

    // ---- main loop ---------------------------------------------------------
    const int wp = tid >> 5, ln = tid & 31;
    const int cg = wp % G,  rg = wp / G;
    const int w0 = cg * TW;
    const int zl = rg * (32 * ZPT) + ln;        // base local z (dz strides by 32)

    const u64* __restrict__ Wg =
        reinterpret_cast<const u64*>(wts + WOFF) + (w0 >> 1);

    u64 acc[TR][TW2];
    #pragma unroll
    for (int k = 0; k < TR; ++k)
        #pragma unroll
        for (int j = 0; j < TW2; ++j)
            acc[k][j] = 0ull;

    #pragma unroll 4
    for (int u = 0; u < MUL; ++u) {
        u64 wv[TW2];
        #pragma unroll
        for (int j = 0; j < TW2; ++j)            // broadcast: all lanes same addr
            wv[j] = __ldg(Wg + (size_t)u * (MUL / 2) + j);
        u64 xv[TR];
        #pragma unroll
        for (int dz = 0; dz < ZPT; ++dz)
            #pragma unroll
            for (int i = 0; i < DIM; ++i)        // 1 wavefront per LDS.32
                xv[dz * DIM + i] = dup2(smem[(zl + dz * 32) * RLP + u * DIM + i]);
        #pragma unroll
        for (int k = 0; k < TR; ++k)
            #pragma unroll
            for (int j = 0; j < TW2; ++j)
                fma2(acc[k][j], xv[k], wv[j]);
    }
    __syncthreads();   // x reads done; reuse buffer for output staging

    // ---- scatter accumulators to irrep layout, then coalesced store -------
    #pragma unroll
    for (int dz = 0; dz < ZPT; ++dz) {
        float* orow = &smem[(zl + dz * 32) * LDO];
        #pragma unroll
        for (int i = 0; i < DIM; ++i)
            #pragma unroll
            for (int j = 0; j < TW2; ++j) {
                float2 v = unpack2(acc[dz * DIM + i][j]);
                orow[(w0 + 2 * j    ) * DIM + i] = v.x;
                orow[(w0 + 2 * j + 1) * DIM + i] = v.y;
            }
    }
    __syncthreads();

    for (int idx = tid; idx < zc * RL2; idx += NT) {
        int z = idx / RL2, c = idx - z * RL2;
        *(float2*)&out[(size_t)(z0 + z) * IN_DIM + XOFF + 2 * c] =
            *(const float2*)&smem[z * LDO + 2 * c];
    }
}

// ---- launcher ---------------------------------------------------------------
template<int MUL, int DIM, int XOFF, int WOFF, int ZPT, int TW>
static void launch_block(const float* x, const float* w, float* out, int batch)
{
    constexpr int G  = MUL / TW;
    constexpr int R  = (NT / 32) / G;
    constexpr int ZT = R * 32 * ZPT;
    constexpr int LDO = MUL * DIM + 2;
    const size_t sm = (size_t)ZT * LDO * sizeof(float);
    auto kfn = irrep_kernel<MUL, DIM, XOFF, WOFF, ZPT, TW>;
    cudaFuncSetAttribute(kfn, cudaFuncAttributeMaxDynamicSharedMemorySize, (int)sm);
    const int grid = (batch + ZT - 1) / ZT;
    const float pw = (float)(1.0 / sqrt((double)MUL));
    kfn<<<grid, NT, sm>>>(x, w, out, batch, pw);
}

extern "C" void kernel_launch(void* const* d_in, const int* in_sizes, int n_in,
                              void* d_out, int out_size)
{
    (void)out_size;
    const float* x = (const float*)d_in[0];
    const float* w = (const float*)d_in[1];
    int xsz = in_sizes[0];
    if (n_in >= 2 && in_sizes[0] == W_NUMEL) {   // robust to input ordering
        x = (const float*)d_in[1];
        w = (const float*)d_in[0];
        xsz = in_sizes[1];
    }
    float* out = (float*)d_out;
    const int batch = xsz / IN_DIM;

    //                 MUL DIM XOFF  WOFF ZPT TW   (ZT, TRxTW2, smem)
    launch_block<128, 1,   0,     0,  4, 16>(x, w, out, batch); // 128z, 4x8, 66.6KB
    launch_block< 64, 3, 128, 16384,  2,  8>(x, w, out, batch); //  64z, 6x4, 49.7KB
    launch_block< 32, 5, 320, 20480,  1,  8>(x, w, out, batch); //  64z, 5x4, 41.5KB
    launch_block< 16, 7, 480, 21504,  1,  8>(x, w, out, batch); // 128z, 7x4, 58.4KB
}

// round 13
// speedup vs baseline: 1.2561x; 1.0397x over previous
#include <cuda_runtime.h>
#include <math.h>

typedef unsigned long long u64;

// ---- packed f32x2 helpers (sm_100+) ----------------------------------------
__device__ __forceinline__ u64 pack2(float lo, float hi) {
    u64 r;
    asm("mov.b64 %0, {%1, %2};" : "=l"(r) : "f"(lo), "f"(hi));
    return r;
}
__device__ __forceinline__ u64 dup2(float a) {
    u64 r;
    asm("mov.b64 %0, {%1, %1};" : "=l"(r) : "f"(a));
    return r;
}
__device__ __forceinline__ void fma2(u64 &d, u64 a, u64 b) {
    asm("fma.rn.f32x2 %0, %1, %2, %0;" : "+l"(d) : "l"(a), "l"(b));
}
__device__ __forceinline__ float2 unpack2(u64 v) {
    float lo, hi;
    asm("mov.b64 {%0, %1}, %2;" : "=f"(lo), "=f"(hi) : "l"(v));
    return make_float2(lo, hi);
}

static constexpr int IN_DIM  = 592;
static constexpr int W_NUMEL = 21760;
static constexpr int NT      = 256;   // 8 warps

// ---- per-CTA row counts (ZT) per irrep block --------------------------------
// block:      MUL DIM  TW ZPT   G  R   ZT  TRxTW2
//   0         128   1  16   3   8  1   96   3x8
//   1          64   3   8   1   8  1   32   3x4
//   2          32   5   8   1   4  2   64   5x4
//   3          16   7   4   1   4  2   64   7x2
static constexpr int ZT0 = 96, ZT1 = 32, ZT2 = 64, ZT3 = 64;

// out[z, w*DIM+i] = pw * sum_u W[u,w] * x[z, u*DIM+i]
//
//  * all lanes of a warp share the same TW weight columns -> W loads are
//    warp-broadcast LDG.128 (float4 -> two f32x2 packs), L1-resident
//  * lanes span 32 consecutive z rows; smem x row stride RLP is ODD so every
//    x LDS.32 is one conflict-free wavefront
//  * per-thread f32x2 register tile TR x TW2 keeps fma demand above L1 demand
template<int MUL, int DIM, int XOFF, int WOFF, int ZPT, int TW>
__device__ __forceinline__
void irrep_block(const float* __restrict__ x,
                 const float* __restrict__ wts,
                 float* __restrict__ out,
                 int batch, int bid, float* smem)
{
    constexpr int NW  = NT / 32;
    constexpr int G   = MUL / TW;      // column groups
    constexpr int R   = NW / G;        // row groups
    constexpr int ZT  = R * 32 * ZPT;  // z rows per CTA
    constexpr int TR  = ZPT * DIM;     // accumulator rows per thread
    constexpr int TW2 = TW / 2;
    constexpr int TW4 = TW / 4;
    constexpr int RL  = MUL * DIM;
    constexpr int RLP = RL + 1;        // odd stride: conflict-free LDS
    constexpr int LDO = RL + 2;        // even stride for output staging
    constexpr int RL4 = RL / 4;
    constexpr int RL2 = RL / 2;
    static_assert(G * R == NW, "warps tile (colgrp x rowgrp)");
    static_assert((TW & 3) == 0, "TW multiple of 4 for LDG.128 W loads");

    const int tid = threadIdx.x;
    const int z0  = bid * ZT;
    const int zc  = min(ZT, batch - z0);
    const float pw = 1.0f / sqrtf((float)MUL);

    // ---- stage x slice (pw folded in), RLP stride --------------------------
    for (int idx = tid; idx < zc * RL4; idx += NT) {
        int z = idx / RL4, c = idx - z * RL4;
        float4 v = *(const float4*)&x[(size_t)(z0 + z) * IN_DIM + XOFF + 4 * c];
        float* p = &smem[z * RLP + 4 * c];
        p[0] = v.x * pw; p[1] = v.y * pw; p[2] = v.z * pw; p[3] = v.w * pw;
    }
    if (zc < ZT) {   // tail CTA: zero so garbage never enters the math
        for (int idx = zc * RLP + tid; idx < ZT * RLP; idx += NT)
            smem[idx] = 0.f;
    }
    __syncthreads();

    // ---- main loop ----------------------------------------------------------
    const int wp = tid >> 5, ln = tid & 31;
    const int cg = wp % G,  rg = wp / G;
    const int w0 = cg * TW;
    const int zl = rg * (32 * ZPT) + ln;

    const float4* __restrict__ W4 =
        reinterpret_cast<const float4*>(wts + WOFF) + (w0 >> 2);
    const float*  Xr = &smem[zl * RLP];

    u64 acc[TR][TW2];
    #pragma unroll
    for (int k = 0; k < TR; ++k)
        #pragma unroll
        for (int j = 0; j < TW2; ++j)
            acc[k][j] = 0ull;

    #pragma unroll 4
    for (int u = 0; u < MUL; ++u) {
        u64 wv[TW2];
        #pragma unroll
        for (int q = 0; q < TW4; ++q) {        // broadcast LDG.128
            float4 wq = __ldg(W4 + (size_t)u * (MUL / 4) + q);
            wv[2 * q    ] = pack2(wq.x, wq.y);
            wv[2 * q + 1] = pack2(wq.z, wq.w);
        }
        u64 xv[TR];
        #pragma unroll
        for (int dz = 0; dz < ZPT; ++dz)
            #pragma unroll
            for (int i = 0; i < DIM; ++i)      // conflict-free LDS.32
                xv[dz * DIM + i] = dup2(Xr[dz * 32 * RLP + u * DIM + i]);
        #pragma unroll
        for (int k = 0; k < TR; ++k)
            #pragma unroll
            for (int j = 0; j < TW2; ++j)
                fma2(acc[k][j], xv[k], wv[j]);
    }
    __syncthreads();   // x reads done; reuse buffer for output staging

    // ---- scatter accumulators to irrep layout, then coalesced store --------
    #pragma unroll
    for (int dz = 0; dz < ZPT; ++dz) {
        float* orow = &smem[(zl + dz * 32) * LDO];
        #pragma unroll
        for (int i = 0; i < DIM; ++i)
            #pragma unroll
            for (int j = 0; j < TW2; ++j) {
                float2 v = unpack2(acc[dz * DIM + i][j]);
                orow[(w0 + 2 * j    ) * DIM + i] = v.x;
                orow[(w0 + 2 * j + 1) * DIM + i] = v.y;
            }
    }
    __syncthreads();

    for (int idx = tid; idx < zc * RL2; idx += NT) {
        int z = idx / RL2, c = idx - z * RL2;
        *(float2*)&out[(size_t)(z0 + z) * IN_DIM + XOFF + 2 * c] =
            *(const float2*)&smem[z * LDO + 2 * c];
    }
}

// ---- fused dispatch kernel ---------------------------------------------------
__global__ __launch_bounds__(NT, 3)
void fused_irrep_kernel(const float* __restrict__ x,
                        const float* __restrict__ wts,
                        float* __restrict__ out,
                        int batch)
{
    extern __shared__ float smem[];
    const int g0 = (batch + ZT0 - 1) / ZT0;
    const int g1 = (batch + ZT1 - 1) / ZT1;
    const int g2 = (batch + ZT2 - 1) / ZT2;
    int bid = blockIdx.x;

    if (bid < g0) {
        irrep_block<128, 1,   0,     0, 3, 16>(x, wts, out, batch, bid, smem);
    } else if ((bid -= g0) < g1) {
        irrep_block< 64, 3, 128, 16384, 1,  8>(x, wts, out, batch, bid, smem);
    } else if ((bid -= g1) < g2) {
        irrep_block< 32, 5, 320, 20480, 1,  8>(x, wts, out, batch, bid, smem);
    } else {
        irrep_block< 16, 7, 480, 21504, 1,  4>(x, wts, out, batch, bid - g2, smem);
    }
}

extern "C" void kernel_launch(void* const* d_in, const int* in_sizes, int n_in,
                              void* d_out, int out_size)
{
    (void)out_size;
    const float* x = (const float*)d_in[0];
    const float* w = (const float*)d_in[1];
    int xsz = in_sizes[0];
    if (n_in >= 2 && in_sizes[0] == W_NUMEL) {   // robust to input ordering
        x = (const float*)d_in[1];
        w = (const float*)d_in[0];
        xsz = in_sizes[1];
    }
    float* out = (float*)d_out;
    const int batch = xsz / IN_DIM;

    const int g0 = (batch + ZT0 - 1) / ZT0;
    const int g1 = (batch + ZT1 - 1) / ZT1;
    const int g2 = (batch + ZT2 - 1) / ZT2;
    const int g3 = (batch + ZT3 - 1) / ZT3;
    const int grid = g0 + g1 + g2 + g3;

    // smem = max over paths of ZT*(RL+2) floats:
    //   b0: 96*130, b1: 32*194, b2: 64*162, b3: 64*114  -> 49920 B
    const int sm = ZT0 * (128 * 1 + 2) * (int)sizeof(float);
    cudaFuncSetAttribute(fused_irrep_kernel,
                         cudaFuncAttributeMaxDynamicSharedMemorySize, sm);
    fused_irrep_kernel<<<grid, NT, sm>>>(x, w, out, batch);
}

// round 14
// speedup vs baseline: 1.5193x; 1.2095x over previous
#include <cuda_runtime.h>
#include <math.h>

typedef unsigned long long u64;

// ---- packed f32x2 helpers (sm_100+) ----------------------------------------
__device__ __forceinline__ u64 pack2(float lo, float hi) {
    u64 r;
    asm("mov.b64 %0, {%1, %2};" : "=l"(r) : "f"(lo), "f"(hi));
    return r;
}
__device__ __forceinline__ u64 dup2(float a) {
    u64 r;
    asm("mov.b64 %0, {%1, %1};" : "=l"(r) : "f"(a));
    return r;
}
__device__ __forceinline__ void fma2(u64 &d, u64 a, u64 b) {
    asm("fma.rn.f32x2 %0, %1, %2, %0;" : "+l"(d) : "l"(a), "l"(b));
}
__device__ __forceinline__ float2 unpack2(u64 v) {
    float lo, hi;
    asm("mov.b64 {%0, %1}, %2;" : "=f"(lo), "=f"(hi) : "l"(v));
    return make_float2(lo, hi);
}

static constexpr int IN_DIM  = 592;
static constexpr int W_NUMEL = 21760;
static constexpr int NT      = 256;   // 8 warps

// per-CTA z rows per block (must match template params below)
static constexpr int ZT0 = 96, ZT1 = 64, ZT2 = 64, ZT3 = 128;

// out[z, w*DIM+i] = pw * sum_u W[u,w] * x[z, u*DIM+i]
//
// Round-13 structure: ZERO global loads in the main loop.
//  * W staged into smem in u-chunks of UC rows; in-loop W reads are
//    broadcast LDS.128 (all lanes same address -> 1 conflict-free wavefront,
//    16B through the crossbar) instead of per-warp LDG.128 (the round-12
//    l1tex saturator).
//  * x staged once (pw folded), odd row stride -> conflict-free LDS.32.
//  * per-thread f32x2 tile TR x TW2; fma demand > crossbar demand in all paths.
template<int MUL, int DIM, int XOFF, int WOFF, int ZPT, int TW, int UC>
__device__ __forceinline__
void irrep_block(const float* __restrict__ x,
                 const float* __restrict__ wts,
                 float* __restrict__ out,
                 int batch, int bid, float* smem)
{
    constexpr int NW   = NT / 32;
    constexpr int G    = MUL / TW;      // column groups
    constexpr int R    = NW / G;        // row groups
    constexpr int ZT   = R * 32 * ZPT;  // z rows per CTA
    constexpr int TR   = ZPT * DIM;     // accumulator rows per thread
    constexpr int TW2  = TW / 2;
    constexpr int TW4  = TW / 4;
    constexpr int RL   = MUL * DIM;
    constexpr int RLP  = RL + 1;        // odd stride: conflict-free LDS
    constexpr int LDO  = RL + 2;        // even stride for output staging
    constexpr int RL4  = RL / 4;
    constexpr int RL2  = RL / 2;
    constexpr int WCH  = UC * MUL;      // W chunk floats
    constexpr int NPASS = MUL / UC;
    static_assert(G * R == NW, "warps tile (colgrp x rowgrp)");
    static_assert((TW & 3) == 0, "TW multiple of 4 for LDS.128 W reads");
    static_assert(NPASS * UC == MUL, "u chunks cover MUL");

    float* Xs  = smem;                  // [ZT][RLP]
    float* Wsm = smem + ZT * RLP;       // [UC][MUL] current chunk

    const int tid = threadIdx.x;
    const int z0  = bid * ZT;
    const int zc  = min(ZT, batch - z0);
    const float pw = 1.0f / sqrtf((float)MUL);

    // ---- stage x slice (pw folded in), RLP stride --------------------------
    for (int idx = tid; idx < zc * RL4; idx += NT) {
        int z = idx / RL4, c = idx - z * RL4;
        float4 v = *(const float4*)&x[(size_t)(z0 + z) * IN_DIM + XOFF + 4 * c];
        float* p = &Xs[z * RLP + 4 * c];
        p[0] = v.x * pw; p[1] = v.y * pw; p[2] = v.z * pw; p[3] = v.w * pw;
    }
    if (zc < ZT) {   // tail CTA: zero so garbage never enters the math
        for (int idx = zc * RLP + tid; idx < ZT * RLP; idx += NT)
            Xs[idx] = 0.f;
    }

    // ---- thread mapping ------------------------------------------------------
    const int wp = tid >> 5, ln = tid & 31;
    const int cg = wp % G,  rg = wp / G;
    const int w0 = cg * TW;
    const int zl = rg * (32 * ZPT) + ln;
    const float* Xr = &Xs[zl * RLP];

    u64 acc[TR][TW2];
    #pragma unroll
    for (int k = 0; k < TR; ++k)
        #pragma unroll
        for (int j = 0; j < TW2; ++j)
            acc[k][j] = 0ull;

    // ---- u-chunked main loop: stage W chunk, then crossbar-only compute -----
    const float4* __restrict__ Wg4 =
        reinterpret_cast<const float4*>(wts + WOFF);

    for (int p = 0; p < NPASS; ++p) {
        __syncthreads();               // prev-pass W reads done (and x staged)
        for (int idx = tid; idx < WCH / 4; idx += NT)
            *(float4*)&Wsm[4 * idx] = __ldg(Wg4 + (size_t)p * (WCH / 4) + idx);
        __syncthreads();

        #pragma unroll 4
        for (int uu = 0; uu < UC; ++uu) {
            const int u = p * UC + uu;
            u64 wv[TW2];
            #pragma unroll
            for (int q = 0; q < TW4; ++q) {    // broadcast LDS.128
                float4 wq = *(const float4*)&Wsm[uu * MUL + w0 + 4 * q];
                wv[2 * q    ] = pack2(wq.x, wq.y);
                wv[2 * q + 1] = pack2(wq.z, wq.w);
            }
            #pragma unroll
            for (int dz = 0; dz < ZPT; ++dz)
                #pragma unroll
                for (int i = 0; i < DIM; ++i) {
                    u64 xv = dup2(Xr[dz * 32 * RLP + u * DIM + i]);
                    #pragma unroll
                    for (int j = 0; j < TW2; ++j)
                        fma2(acc[dz * DIM + i][j], xv, wv[j]);
                }
        }
    }
    __syncthreads();   // x/W reads done; reuse buffer for output staging

    // ---- scatter accumulators to irrep layout, then coalesced store --------
    #pragma unroll
    for (int dz = 0; dz < ZPT; ++dz) {
        float* orow = &smem[(zl + dz * 32) * LDO];
        #pragma unroll
        for (int i = 0; i < DIM; ++i)
            #pragma unroll
            for (int j = 0; j < TW2; ++j) {
                float2 v = unpack2(acc[dz * DIM + i][j]);
                orow[(w0 + 2 * j    ) * DIM + i] = v.x;
                orow[(w0 + 2 * j + 1) * DIM + i] = v.y;
            }
    }
    __syncthreads();

    for (int idx = tid; idx < zc * RL2; idx += NT) {
        int z = idx / RL2, c = idx - z * RL2;
        *(float2*)&out[(size_t)(z0 + z) * IN_DIM + XOFF + 2 * c] =
            *(const float2*)&smem[z * LDO + 2 * c];
    }
}

// ---- fused dispatch kernel ---------------------------------------------------
__global__ __launch_bounds__(NT, 3)
void fused_irrep_kernel(const float* __restrict__ x,
                        const float* __restrict__ wts,
                        float* __restrict__ out,
                        int batch)
{
    extern __shared__ float smem[];
    const int g0 = (batch + ZT0 - 1) / ZT0;
    const int g1 = (batch + ZT1 - 1) / ZT1;
    const int g2 = (batch + ZT2 - 1) / ZT2;
    int bid = blockIdx.x;

    //                MUL DIM XOFF  WOFF ZPT TW  UC
    if (bid < g0) {
        irrep_block<128, 1,   0,     0, 3, 16, 32>(x, wts, out, batch, bid, smem);
    } else if ((bid -= g0) < g1) {
        irrep_block< 64, 3, 128, 16384, 2,  8, 64>(x, wts, out, batch, bid, smem);
    } else if ((bid -= g1) < g2) {
        irrep_block< 32, 5, 320, 20480, 1,  8, 32>(x, wts, out, batch, bid, smem);
    } else {
        irrep_block< 16, 7, 480, 21504, 1,  8, 16>(x, wts, out, batch, bid - g2, smem);
    }
}

extern "C" void kernel_launch(void* const* d_in, const int* in_sizes, int n_in,
                              void* d_out, int out_size)
{
    (void)out_size;
    const float* x = (const float*)d_in[0];
    const float* w = (const float*)d_in[1];
    int xsz = in_sizes[0];
    if (n_in >= 2 && in_sizes[0] == W_NUMEL) {   // robust to input ordering
        x = (const float*)d_in[1];
        w = (const float*)d_in[0];
        xsz = in_sizes[1];
    }
    float* out = (float*)d_out;
    const int batch = xsz / IN_DIM;

    const int g0 = (batch + ZT0 - 1) / ZT0;
    const int g1 = (batch + ZT1 - 1) / ZT1;
    const int g2 = (batch + ZT2 - 1) / ZT2;
    const int g3 = (batch + ZT3 - 1) / ZT3;
    const int grid = g0 + g1 + g2 + g3;

    // smem (floats), max over paths of x + W chunk:
    //   b0: 96*129 + 32*128 = 16480   b1: 64*193 + 64*64 = 16448
    //   b2: 64*161 + 32*32  = 11328   b3: 128*113 + 16*16 = 14720
    const int sm = 16480 * (int)sizeof(float);   // 65920 B -> 3 CTAs/SM
    cudaFuncSetAttribute(fused_irrep_kernel,
                         cudaFuncAttributeMaxDynamicSharedMemorySize, sm);
    fused_irrep_kernel<<<grid, NT, sm>>>(x, w, out, batch);
}